// round 6
// baseline (speedup 1.0000x reference)
#include <cuda_runtime.h>
#include <cuda_bf16.h>
#include <cstdint>

#define M_ROWS 16384
#define KD 256
#define NC 8192
#define QUANT_ELEMS 4194304
#define ONEHOT_ELEMS 134217728
#define NCAND 64
#define THRM 2.5e-4f

__device__ float g_A[M_ROWS * KD];           // inputs transposed [row][dim] fp32
__device__ float g_xsq[M_ROWS];
__device__ int   g_idx[M_ROWS];
__device__ int   g_cnt[M_ROWS];
__device__ int   g_cand[M_ROWS * NCAND];
__device__ __nv_bfloat16 g_Ab[M_ROWS * KD];  // bf16 copy of A
__device__ __nv_bfloat16 g_Bb[NC * KD];      // bf16 copy of codebook

// ---------------- PTX helpers (sm_80-era only; no 'a' features) ----------------
__device__ __forceinline__ uint32_t smem_u32(const void* p) {
    uint32_t a;
    asm("{ .reg .u64 t; cvta.to.shared.u64 t, %1; cvt.u32.u64 %0, t; }" : "=r"(a) : "l"(p));
    return a;
}
#define CP_ASYNC16(dst, src) \
    asm volatile("cp.async.cg.shared.global [%0], [%1], 16;" :: "r"(dst), "l"(src) : "memory")
#define CP_COMMIT() asm volatile("cp.async.commit_group;" ::: "memory")
#define CP_WAIT(n)  asm volatile("cp.async.wait_group %0;" :: "n"(n) : "memory")

__device__ __forceinline__ void ldm_x4(uint32_t* r, uint32_t addr) {
    asm volatile("ldmatrix.sync.aligned.m8n8.x4.shared.b16 {%0,%1,%2,%3}, [%4];"
                 : "=r"(r[0]), "=r"(r[1]), "=r"(r[2]), "=r"(r[3]) : "r"(addr));
}
__device__ __forceinline__ void mma16816(float* d, const uint32_t* a, const uint32_t* b) {
    asm volatile("mma.sync.aligned.m16n8k16.row.col.f32.bf16.bf16.f32 "
                 "{%0,%1,%2,%3}, {%4,%5,%6,%7}, {%8,%9}, {%0,%1,%2,%3};"
                 : "+f"(d[0]), "+f"(d[1]), "+f"(d[2]), "+f"(d[3])
                 : "r"(a[0]), "r"(a[1]), "r"(a[2]), "r"(a[3]), "r"(b[0]), "r"(b[1]));
}
__device__ __forceinline__ uint32_t swz(uint32_t byte) {
    return byte ^ ((byte >> 5) & 0x70u);
}

// ---------------- prep kernels ----------------
__global__ void k_transpose(const float* __restrict__ in) {
    __shared__ float tile[32][33];
    int b = blockIdx.z, c0 = blockIdx.y * 32, hw0 = blockIdx.x * 32;
    int tx = threadIdx.x, ty = threadIdx.y;
#pragma unroll
    for (int i = 0; i < 4; i++)
        tile[ty + i * 8][tx] = in[(b * 256 + c0 + ty + i * 8) * 1024 + hw0 + tx];
    __syncthreads();
#pragma unroll
    for (int i = 0; i < 4; i++) {
        float v = tile[tx][ty + i * 8];
        size_t o = (size_t)(b * 1024 + hw0 + ty + i * 8) * 256 + c0 + tx;
        g_A[o] = v;
        g_Ab[o] = __float2bfloat16(v);
    }
}

__global__ void k_xsq() {   // also zeroes candidate counters
    int warp = threadIdx.x >> 5, lane = threadIdx.x & 31;
    int row = blockIdx.x * 8 + warp;
    const float* p = g_A + (size_t)row * 256;
    float s = 0.f;
#pragma unroll
    for (int i = 0; i < 8; i++) { float v = p[lane + i * 32]; s = __fmaf_rn(v, v, s); }
#pragma unroll
    for (int o = 16; o; o >>= 1) s += __shfl_xor_sync(0xffffffffu, s, o);
    if (lane == 0) { g_xsq[row] = s; g_cnt[row] = 0; }
}

__global__ void k_bprep(const float* __restrict__ cb) {
    int t = blockIdx.x * 256 + threadIdx.x;
    float2 v = ((const float2*)cb)[t];
    __nv_bfloat162 h;
    h.x = __float2bfloat16(v.x);
    h.y = __float2bfloat16(v.y);
    ((__nv_bfloat162*)g_Bb)[t] = h;
}

// ---------------- GEMM + fused argmin/candidate recording ----------------
#define SM_A  0u
#define SM_B0 65536u
#define SM_B1 131072u
#define SM_RMIN 196608u
#define GEMM_SMEM (196608 + 512 + 1024)

__global__ void __launch_bounds__(256, 1) k_gemm() {
    extern __shared__ char smem[];
    uint32_t sb = (smem_u32(smem) + 1023u) & ~1023u;
    unsigned* s_rmin = (unsigned*)(smem + (sb - smem_u32(smem)) + SM_RMIN);
    int tid = threadIdx.x;
    int lane = tid & 31, wid = tid >> 5;
    int wm = wid & 3, wn = wid >> 2;
    int m0 = blockIdx.x * 128;

    // init running row-min (positive dists -> uint bit order == float order)
    if (tid < 128) s_rmin[tid] = 0x7f7fffffu;

    // prologue: A tile + first two B chunks
    {
        const __nv_bfloat16* srcA = g_Ab + (size_t)m0 * KD;
#pragma unroll
        for (int i = 0; i < 16; i++) {
            int idx = i * 256 + tid, r = idx >> 5, cc = idx & 31;
            CP_ASYNC16(sb + SM_A + swz(r * 512 + cc * 16),
                       (const char*)(srcA + r * 256 + cc * 8));
        }
#pragma unroll
        for (int i = 0; i < 16; i++) {
            int idx = i * 256 + tid, r = idx >> 5, cc = idx & 31;
            CP_ASYNC16(sb + SM_B0 + swz(r * 512 + cc * 16),
                       (const char*)(g_Bb + r * 256 + cc * 8));
        }
        CP_COMMIT();
        const __nv_bfloat16* srcB1 = g_Bb + 128 * 256;
#pragma unroll
        for (int i = 0; i < 16; i++) {
            int idx = i * 256 + tid, r = idx >> 5, cc = idx & 31;
            CP_ASYNC16(sb + SM_B1 + swz(r * 512 + cc * 16),
                       (const char*)(srcB1 + r * 256 + cc * 8));
        }
        CP_COMMIT();
    }

    int rloc0 = wm * 32 + (lane >> 2);      // CTA-local row base
    float xsv[2][2];
#pragma unroll
    for (int mt = 0; mt < 2; mt++) {
        xsv[mt][0] = g_xsq[m0 + rloc0 + mt * 16];
        xsv[mt][1] = g_xsq[m0 + rloc0 + mt * 16 + 8];
    }

    uint32_t aRow = (uint32_t)(wm * 32 + (lane & 15));
    uint32_t aXor = (aRow & 7u) << 4;
    uint32_t aCfix = (uint32_t)((lane >> 4) * 16);
    uint32_t aBase[2] = { sb + SM_A + aRow * 512, sb + SM_A + (aRow + 16) * 512 };
    uint32_t bRow = (uint32_t)(wn * 64 + ((lane >> 4) * 8) + (lane & 7));
    uint32_t bXor = (bRow & 7u) << 4;
    uint32_t bCfix = (uint32_t)(((lane >> 3) & 1) * 16);

    float acc[2][8][4];
#pragma unroll
    for (int mt = 0; mt < 2; mt++)
#pragma unroll
        for (int nt = 0; nt < 8; nt++)
#pragma unroll
            for (int q = 0; q < 4; q++) acc[mt][nt][q] = 0.f;

    for (int s = 0; s < 64; s++) {
        if (s < 63) CP_WAIT(1); else CP_WAIT(0);
        __syncthreads();
        uint32_t bufB = sb + ((s & 1) ? SM_B1 : SM_B0);

#pragma unroll 4
        for (int ks = 0; ks < 16; ks++) {
            uint32_t kb = (uint32_t)(ks * 32);
            uint32_t a[2][4];
#pragma unroll
            for (int mt = 0; mt < 2; mt++)
                ldm_x4(a[mt], aBase[mt] + ((kb + aCfix) ^ aXor));
            uint32_t b[4][4];
#pragma unroll
            for (int p = 0; p < 4; p++)
                ldm_x4(b[p], bufB + (bRow + p * 16) * 512 + ((kb + bCfix) ^ bXor));
#pragma unroll
            for (int mt = 0; mt < 2; mt++)
#pragma unroll
                for (int nt = 0; nt < 8; nt++)
                    mma16816(acc[mt][nt], a[mt], &b[nt >> 1][(nt & 1) * 2]);
        }
        __syncthreads();

        if (s + 2 < 64) {
            const __nv_bfloat16* srcB = g_Bb + (size_t)(s + 2) * 128 * 256;
#pragma unroll
            for (int i = 0; i < 16; i++) {
                int idx = i * 256 + tid, r = idx >> 5, cc = idx & 31;
                CP_ASYNC16(bufB + swz(r * 512 + cc * 16),
                           (const char*)(srcB + r * 256 + cc * 8));
            }
            CP_COMMIT();
        }

        // ---- epilogue: sync-free, stale-threshold candidate recording ----
        // dist in place
#pragma unroll
        for (int mt = 0; mt < 2; mt++)
#pragma unroll
            for (int nt = 0; nt < 8; nt++) {
                acc[mt][nt][0] = __fmaf_rn(-2.f, acc[mt][nt][0], xsv[mt][0]);
                acc[mt][nt][1] = __fmaf_rn(-2.f, acc[mt][nt][1], xsv[mt][0]);
                acc[mt][nt][2] = __fmaf_rn(-2.f, acc[mt][nt][2], xsv[mt][1]);
                acc[mt][nt][3] = __fmaf_rn(-2.f, acc[mt][nt][3], xsv[mt][1]);
            }
        int cbase = s * 128 + wn * 64 + (lane & 3) * 2;
#pragma unroll
        for (int mt = 0; mt < 2; mt++)
#pragma unroll
            for (int h = 0; h < 2; h++) {
                int rl = rloc0 + mt * 16 + h * 8;
                // per-thread chunk min over this row-group (16 values)
                float lm = 3.4e38f;
#pragma unroll
                for (int nt = 0; nt < 8; nt++)
                    lm = fminf(lm, fminf(acc[mt][nt][h * 2], acc[mt][nt][h * 2 + 1]));
                // quad reduce (lanes sharing the same row)
                float qm = lm;
                qm = fminf(qm, __shfl_xor_sync(0xffffffffu, qm, 1));
                qm = fminf(qm, __shfl_xor_sync(0xffffffffu, qm, 2));
                if ((lane & 3) == 0)
                    atomicMin(&s_rmin[rl], __float_as_uint(qm));
                // stale read is a monotone upper bound of the final min -> superset
                float thr = fminf(__uint_as_float(s_rmin[rl]), qm) + THRM;
                int rg = m0 + rl;
#pragma unroll
                for (int nt = 0; nt < 8; nt++) {
#pragma unroll
                    for (int e = 0; e < 2; e++) {
                        float v = acc[mt][nt][h * 2 + e];
                        if (v <= thr) {
                            int slot = atomicAdd(&g_cnt[rg], 1);
                            if (slot < NCAND)
                                g_cand[rg * NCAND + slot] = cbase + nt * 8 + e;
                        }
                        acc[mt][nt][h * 2 + e] = 0.f;   // reset for next chunk
                    }
                }
            }
    }
}

// ---------------- decide: exact rescan of recorded candidates ----------------
__global__ void __launch_bounds__(256) k_decide(const float* __restrict__ cb) {
    int wid = threadIdx.x >> 5, lane = threadIdx.x & 31;
    int row = blockIdx.x * 8 + wid;
    int cnt = g_cnt[row];
    const float* x = g_A + (size_t)row * 256;
    float xsvr = g_xsq[row];
    unsigned long long bk = 0xffffffffffffffffull;

    if (cnt > 0 && cnt <= NCAND) {
        for (int c = lane; c < cnt; c += 32) {
            int col = g_cand[row * NCAND + c];
            const float* cp = cb + (size_t)col * 256;
            float sacc = 0.f;
            for (int k = 0; k < 256; k++) sacc = __fmaf_rn(x[k], cp[k], sacc);
            float de = __fmaf_rn(-2.f, sacc, xsvr);
            unsigned long long key =
                ((unsigned long long)__float_as_uint(de) << 32) | (unsigned)col;
            if (key < bk) bk = key;
        }
    } else {   // overflow / empty: exact full scan (prob ~0)
        for (int col = lane; col < NC; col += 32) {
            const float* cp = cb + (size_t)col * 256;
            float sacc = 0.f;
            for (int k = 0; k < 256; k++) sacc = __fmaf_rn(x[k], cp[k], sacc);
            float de = __fmaf_rn(-2.f, sacc, xsvr);
            unsigned long long key =
                ((unsigned long long)__float_as_uint(de) << 32) | (unsigned)col;
            if (key < bk) bk = key;
        }
    }
#pragma unroll
    for (int o = 16; o; o >>= 1) {
        unsigned long long t2 = __shfl_xor_sync(0xffffffffu, bk, o);
        if (t2 < bk) bk = t2;
    }
    if (lane == 0) g_idx[row] = (int)(bk & 0xffffffffu);
}

// ---------------- outputs ----------------
__global__ void k_quant(const float* __restrict__ cb, float* __restrict__ out) {
    int t = blockIdx.x * 256 + threadIdx.x;
    int b = t >> 18, rem = t & 262143;
    int d = rem >> 10, hw = rem & 1023;
    int idx = g_idx[(b << 10) + hw];
    out[t] = cb[(size_t)idx * 256 + d];
}

__global__ void k_onehot(float* __restrict__ out) {
    int t = blockIdx.x * 256 + threadIdx.x;
    int n = t >> 11, q = t & 2047;
    int idx = g_idx[n];
    int base = q << 2;
    float4 v;
    v.x = (idx == base + 0) ? 1.f : 0.f;
    v.y = (idx == base + 1) ? 1.f : 0.f;
    v.z = (idx == base + 2) ? 1.f : 0.f;
    v.w = (idx == base + 3) ? 1.f : 0.f;
    ((float4*)out)[t] = v;
}

extern "C" void kernel_launch(void* const* d_in, const int* in_sizes, int n_in,
                              void* d_out, int out_size) {
    const float* inputs = (const float*)d_in[0];
    const float* cb     = (const float*)d_in[1];
    if (n_in >= 2 && in_sizes[0] == NC * KD && in_sizes[1] == QUANT_ELEMS) {
        inputs = (const float*)d_in[1];
        cb     = (const float*)d_in[0];
    }
    float* out = (float*)d_out;

    cudaFuncSetAttribute(k_gemm, cudaFuncAttributeMaxDynamicSharedMemorySize, GEMM_SMEM);

    k_transpose<<<dim3(32, 8, 16), dim3(32, 8)>>>(inputs);
    k_xsq<<<M_ROWS / 8, 256>>>();
    k_bprep<<<NC * KD / 2 / 256, 256>>>(cb);
    k_gemm<<<128, 256, GEMM_SMEM>>>();
    k_decide<<<M_ROWS / 8, 256>>>(cb);
    k_quant<<<QUANT_ELEMS / 256, 256>>>(cb, out);
    k_onehot<<<(ONEHOT_ELEMS / 4) / 256, 256>>>(out + QUANT_ELEMS);
}

// round 7
// speedup vs baseline: 1.3846x; 1.3846x over previous
#include <cuda_runtime.h>
#include <cuda_bf16.h>
#include <cstdint>

#define M_ROWS 16384
#define KD 256
#define NC 8192
#define QUANT_ELEMS 4194304
#define ONEHOT_ELEMS 134217728
#define THRM 2.5e-4f

__device__ float g_A[M_ROWS * KD];           // inputs transposed [row][dim] fp32
__device__ float g_xsq[M_ROWS];
__device__ int   g_idx[M_ROWS];
__device__ uint2 g_pairs[M_ROWS * 32];       // per-row 32 (distbits, col) pairs
__device__ __nv_bfloat16 g_Ab[M_ROWS * KD];  // bf16 copy of A
__device__ __nv_bfloat16 g_Bb[NC * KD];      // bf16 copy of codebook

// ---------------- PTX helpers (sm_80-era only; no 'a' features) ----------------
__device__ __forceinline__ uint32_t smem_u32(const void* p) {
    uint32_t a;
    asm("{ .reg .u64 t; cvta.to.shared.u64 t, %1; cvt.u32.u64 %0, t; }" : "=r"(a) : "l"(p));
    return a;
}
#define CP_ASYNC16(dst, src) \
    asm volatile("cp.async.cg.shared.global [%0], [%1], 16;" :: "r"(dst), "l"(src) : "memory")
#define CP_COMMIT() asm volatile("cp.async.commit_group;" ::: "memory")
#define CP_WAIT(n)  asm volatile("cp.async.wait_group %0;" :: "n"(n) : "memory")

__device__ __forceinline__ void ldm_x4(uint32_t* r, uint32_t addr) {
    asm volatile("ldmatrix.sync.aligned.m8n8.x4.shared.b16 {%0,%1,%2,%3}, [%4];"
                 : "=r"(r[0]), "=r"(r[1]), "=r"(r[2]), "=r"(r[3]) : "r"(addr));
}
__device__ __forceinline__ void mma16816(float* d, const uint32_t* a, const uint32_t* b) {
    asm volatile("mma.sync.aligned.m16n8k16.row.col.f32.bf16.bf16.f32 "
                 "{%0,%1,%2,%3}, {%4,%5,%6,%7}, {%8,%9}, {%0,%1,%2,%3};"
                 : "+f"(d[0]), "+f"(d[1]), "+f"(d[2]), "+f"(d[3])
                 : "r"(a[0]), "r"(a[1]), "r"(a[2]), "r"(a[3]), "r"(b[0]), "r"(b[1]));
}
__device__ __forceinline__ uint32_t swz(uint32_t byte) {
    return byte ^ ((byte >> 5) & 0x70u);
}

// ---------------- prep kernels ----------------
__global__ void k_transpose(const float* __restrict__ in) {
    __shared__ float tile[32][33];
    int b = blockIdx.z, c0 = blockIdx.y * 32, hw0 = blockIdx.x * 32;
    int tx = threadIdx.x, ty = threadIdx.y;
#pragma unroll
    for (int i = 0; i < 4; i++)
        tile[ty + i * 8][tx] = in[(b * 256 + c0 + ty + i * 8) * 1024 + hw0 + tx];
    __syncthreads();
#pragma unroll
    for (int i = 0; i < 4; i++) {
        float v = tile[tx][ty + i * 8];
        size_t o = (size_t)(b * 1024 + hw0 + ty + i * 8) * 256 + c0 + tx;
        g_A[o] = v;
        g_Ab[o] = __float2bfloat16(v);
    }
}

__global__ void k_xsq() {
    int warp = threadIdx.x >> 5, lane = threadIdx.x & 31;
    int row = blockIdx.x * 8 + warp;
    const float* p = g_A + (size_t)row * 256;
    float s = 0.f;
#pragma unroll
    for (int i = 0; i < 8; i++) { float v = p[lane + i * 32]; s = __fmaf_rn(v, v, s); }
#pragma unroll
    for (int o = 16; o; o >>= 1) s += __shfl_xor_sync(0xffffffffu, s, o);
    if (lane == 0) g_xsq[row] = s;
}

__global__ void k_bprep(const float* __restrict__ cb) {
    int t = blockIdx.x * 256 + threadIdx.x;
    float2 v = ((const float2*)cb)[t];
    __nv_bfloat162 h;
    h.x = __float2bfloat16(v.x);
    h.y = __float2bfloat16(v.y);
    ((__nv_bfloat162*)g_Bb)[t] = h;
}

// ---------------- GEMM + register-resident top-2 per thread ----------------
// 128 CTAs, 512 threads (16 warps: 4m x 4n). CTA = 128 rows x 8192 cols,
// processed in 64 chunks of 128 cols. smem: A 64KB + B 2x64KB double buffer.
#define SM_A  0u
#define SM_B0 65536u
#define SM_B1 131072u
#define GEMM_SMEM (196608 + 1024)

__global__ void __launch_bounds__(512, 1) k_gemm() {
    extern __shared__ char smem[];
    uint32_t sb = (smem_u32(smem) + 1023u) & ~1023u;
    int tid = threadIdx.x;
    int lane = tid & 31, wid = tid >> 5;
    int wm = wid & 3, wn = wid >> 2;           // 4 warps m, 4 warps n
    int m0 = blockIdx.x * 128;

    // prologue: A tile + first two B chunks
    {
        const __nv_bfloat16* srcA = g_Ab + (size_t)m0 * KD;
#pragma unroll
        for (int i = 0; i < 8; i++) {
            int idx = i * 512 + tid, r = idx >> 5, cc = idx & 31;
            CP_ASYNC16(sb + SM_A + swz(r * 512 + cc * 16),
                       (const char*)(srcA + r * 256 + cc * 8));
        }
#pragma unroll
        for (int i = 0; i < 8; i++) {
            int idx = i * 512 + tid, r = idx >> 5, cc = idx & 31;
            CP_ASYNC16(sb + SM_B0 + swz(r * 512 + cc * 16),
                       (const char*)(g_Bb + r * 256 + cc * 8));
        }
        CP_COMMIT();
        const __nv_bfloat16* srcB1 = g_Bb + 128 * 256;
#pragma unroll
        for (int i = 0; i < 8; i++) {
            int idx = i * 512 + tid, r = idx >> 5, cc = idx & 31;
            CP_ASYNC16(sb + SM_B1 + swz(r * 512 + cc * 16),
                       (const char*)(srcB1 + r * 256 + cc * 8));
        }
        CP_COMMIT();
    }

    int rloc0 = wm * 32 + (lane >> 2);         // CTA-local row base
    float xsv[2][2];
#pragma unroll
    for (int mt = 0; mt < 2; mt++) {
        xsv[mt][0] = g_xsq[m0 + rloc0 + mt * 16];
        xsv[mt][1] = g_xsq[m0 + rloc0 + mt * 16 + 8];
    }

    uint32_t aRow = (uint32_t)(wm * 32 + (lane & 15));
    uint32_t aXor = (aRow & 7u) << 4;
    uint32_t aCfix = (uint32_t)((lane >> 4) * 16);
    uint32_t aBase[2] = { sb + SM_A + aRow * 512, sb + SM_A + (aRow + 16) * 512 };
    uint32_t bRow = (uint32_t)(wn * 32 + ((lane >> 4) * 8) + (lane & 7));
    uint32_t bXor = (bRow & 7u) << 4;
    uint32_t bCfix = (uint32_t)(((lane >> 3) & 1) * 16);

    float acc[2][4][4];
#pragma unroll
    for (int mt = 0; mt < 2; mt++)
#pragma unroll
        for (int nt = 0; nt < 4; nt++)
#pragma unroll
            for (int q = 0; q < 4; q++) acc[mt][nt][q] = 0.f;

    // per-row (4 rows/thread) running min + second-min, with columns
    float m1[2][2], m2[2][2];
    int c1[2][2], c2[2][2];
#pragma unroll
    for (int mt = 0; mt < 2; mt++)
#pragma unroll
        for (int h = 0; h < 2; h++) {
            m1[mt][h] = 3.4e38f; m2[mt][h] = 3.4e38f;
            c1[mt][h] = 0; c2[mt][h] = 0;
        }

    for (int s = 0; s < 64; s++) {
        if (s < 63) CP_WAIT(1); else CP_WAIT(0);
        __syncthreads();
        uint32_t bufB = sb + ((s & 1) ? SM_B1 : SM_B0);

#pragma unroll 4
        for (int ks = 0; ks < 16; ks++) {
            uint32_t kb = (uint32_t)(ks * 32);
            uint32_t a[2][4];
#pragma unroll
            for (int mt = 0; mt < 2; mt++)
                ldm_x4(a[mt], aBase[mt] + ((kb + aCfix) ^ aXor));
            uint32_t b[2][4];
#pragma unroll
            for (int p = 0; p < 2; p++)
                ldm_x4(b[p], bufB + (bRow + p * 16) * 512 + ((kb + bCfix) ^ bXor));
#pragma unroll
            for (int mt = 0; mt < 2; mt++)
#pragma unroll
                for (int nt = 0; nt < 4; nt++)
                    mma16816(acc[mt][nt], a[mt], &b[nt >> 1][(nt & 1) * 2]);
        }
        __syncthreads();

        if (s + 2 < 64) {
            const __nv_bfloat16* srcB = g_Bb + (size_t)(s + 2) * 128 * 256;
#pragma unroll
            for (int i = 0; i < 8; i++) {
                int idx = i * 512 + tid, r = idx >> 5, cc = idx & 31;
                CP_ASYNC16(bufB + swz(r * 512 + cc * 16),
                           (const char*)(srcB + r * 256 + cc * 8));
            }
            CP_COMMIT();
        }

        // ---- epilogue: pure register top-2 update, no smem/atomics/sync ----
        int cbase = s * 128 + wn * 32 + (lane & 3) * 2;
#pragma unroll
        for (int mt = 0; mt < 2; mt++)
#pragma unroll
            for (int h = 0; h < 2; h++) {
                float xq = xsv[mt][h];
#pragma unroll
                for (int nt = 0; nt < 4; nt++) {
#pragma unroll
                    for (int e = 0; e < 2; e++) {
                        float v = __fmaf_rn(-2.f, acc[mt][nt][h * 2 + e], xq);
                        int col = cbase + nt * 8 + e;
                        if (v < m1[mt][h]) {
                            m2[mt][h] = m1[mt][h]; c2[mt][h] = c1[mt][h];
                            m1[mt][h] = v;         c1[mt][h] = col;
                        } else if (v < m2[mt][h]) {
                            m2[mt][h] = v;         c2[mt][h] = col;
                        }
                        acc[mt][nt][h * 2 + e] = 0.f;
                    }
                }
            }
    }

    // write per-thread top-2 pairs: 32 pairs per row
    int slot = wn * 4 + (lane & 3);
#pragma unroll
    for (int mt = 0; mt < 2; mt++)
#pragma unroll
        for (int h = 0; h < 2; h++) {
            int rg = m0 + rloc0 + mt * 16 + h * 8;
            uint2 p1, p2;
            p1.x = __float_as_uint(m1[mt][h]); p1.y = (unsigned)c1[mt][h];
            p2.x = __float_as_uint(m2[mt][h]); p2.y = (unsigned)c2[mt][h];
            g_pairs[rg * 32 + slot * 2 + 0] = p1;
            g_pairs[rg * 32 + slot * 2 + 1] = p2;
        }
}

// ---------------- decide: exact rescan of near-min pairs ----------------
__global__ void __launch_bounds__(256) k_decide(const float* __restrict__ cb) {
    int wid = threadIdx.x >> 5, lane = threadIdx.x & 31;
    int row = blockIdx.x * 8 + wid;
    uint2 pr = g_pairs[row * 32 + lane];
    // warp min of bf16-dist (positive floats: uint order == float order)
    unsigned mv = pr.x;
#pragma unroll
    for (int o = 16; o; o >>= 1) mv = min(mv, __shfl_xor_sync(0xffffffffu, mv, o));
    float thr = __uint_as_float(mv) + THRM;

    unsigned long long bk = 0xffffffffffffffffull;
    if (__uint_as_float(pr.x) <= thr) {
        const float* x = g_A + (size_t)row * 256;
        const float* cp = cb + (size_t)pr.y * 256;
        float sacc = 0.f;
        for (int k = 0; k < 256; k++) sacc = __fmaf_rn(x[k], cp[k], sacc);
        float de = __fmaf_rn(-2.f, sacc, g_xsq[row]);   // == reference fp32 dist
        bk = ((unsigned long long)__float_as_uint(de) << 32) | pr.y;
    }
#pragma unroll
    for (int o = 16; o; o >>= 1) {
        unsigned long long t2 = __shfl_xor_sync(0xffffffffu, bk, o);
        if (t2 < bk) bk = t2;
    }
    if (lane == 0) g_idx[row] = (int)(bk & 0xffffffffu);
}

// ---------------- outputs ----------------
__global__ void k_quant(const float* __restrict__ cb, float* __restrict__ out) {
    int t = blockIdx.x * 256 + threadIdx.x;
    int b = t >> 18, rem = t & 262143;
    int d = rem >> 10, hw = rem & 1023;
    int idx = g_idx[(b << 10) + hw];
    out[t] = cb[(size_t)idx * 256 + d];
}

__global__ void k_onehot(float* __restrict__ out) {
    int t = blockIdx.x * 256 + threadIdx.x;
    int n = t >> 11, q = t & 2047;
    int idx = g_idx[n];
    int base = q << 2;
    float4 v;
    v.x = (idx == base + 0) ? 1.f : 0.f;
    v.y = (idx == base + 1) ? 1.f : 0.f;
    v.z = (idx == base + 2) ? 1.f : 0.f;
    v.w = (idx == base + 3) ? 1.f : 0.f;
    ((float4*)out)[t] = v;
}

extern "C" void kernel_launch(void* const* d_in, const int* in_sizes, int n_in,
                              void* d_out, int out_size) {
    const float* inputs = (const float*)d_in[0];
    const float* cb     = (const float*)d_in[1];
    if (n_in >= 2 && in_sizes[0] == NC * KD && in_sizes[1] == QUANT_ELEMS) {
        inputs = (const float*)d_in[1];
        cb     = (const float*)d_in[0];
    }
    float* out = (float*)d_out;

    cudaFuncSetAttribute(k_gemm, cudaFuncAttributeMaxDynamicSharedMemorySize, GEMM_SMEM);

    k_transpose<<<dim3(32, 8, 16), dim3(32, 8)>>>(inputs);
    k_xsq<<<M_ROWS / 8, 256>>>();
    k_bprep<<<NC * KD / 2 / 256, 256>>>(cb);
    k_gemm<<<128, 512, GEMM_SMEM>>>();
    k_decide<<<M_ROWS / 8, 256>>>(cb);
    k_quant<<<QUANT_ELEMS / 256, 256>>>(cb, out);
    k_onehot<<<(ONEHOT_ELEMS / 4) / 256, 256>>>(out + QUANT_ELEMS);
}